// round 2
// baseline (speedup 1.0000x reference)
#include <cuda_runtime.h>

// Problem constants (fixed by the dataset)
constexpr int NN   = 50000;
constexpr int EE   = 1600000;
constexpr int ET   = EE + NN;     // edges + self loops
constexpr int DIN  = 32;
constexpr int HID  = 64;
constexpr int HEADS= 4;
constexpr int F2   = HEADS * HID; // 256
constexpr int DOUT = 32;

// ---------------- scratch (device globals; no allocation allowed) -----------
__device__ float g_hx [NN * HID];   // x @ W_gcn
__device__ float g_h1 [NN * HID];   // relu(gcn)
__device__ float g_hg [NN * F2];    // h1 @ W_gat
__device__ float g_out2[NN * F2];   // relu(gat)
__device__ float g_as [NN * HEADS];
__device__ float g_ad [NN * HEADS];
__device__ float g_dinv[NN];
__device__ int   g_deg [NN];
__device__ int   g_rowptr[NN + 1];
__device__ int   g_cursor[NN];
__device__ int   g_csr[ET];

// ---------------- CSR build -------------------------------------------------
__global__ void init_kernel() {
    int i = blockIdx.x * blockDim.x + threadIdx.x;
    if (i < NN) { g_deg[i] = 1; g_cursor[i] = 0; }   // self-loop counted
}

__global__ void deg_kernel(const int* __restrict__ ei) {
    int i = blockIdx.x * blockDim.x + threadIdx.x;
    if (i >= EE) return;
    int d = ei[EE + i];
    d = min(max(d, 0), NN - 1);             // defensive clamp (cold path)
    atomicAdd(&g_deg[d], 1);
}

// single-block exclusive scan over degrees -> rowptr
__global__ void scan_kernel() {
    __shared__ int sh[1024];
    const int C = 49;                       // 1024*49 = 50176 >= NN
    int t = threadIdx.x;
    int start = t * C;
    int end   = min(start + C, NN);
    int sum = 0;
    for (int i = start; i < end; ++i) sum += g_deg[i];
    sh[t] = sum;
    __syncthreads();
    for (int off = 1; off < 1024; off <<= 1) {
        int v = (t >= off) ? sh[t - off] : 0;
        __syncthreads();
        sh[t] += v;
        __syncthreads();
    }
    int run = sh[t] - sum;                  // exclusive prefix
    for (int i = start; i < end; ++i) { g_rowptr[i] = run; run += g_deg[i]; }
    if (t == 1023) g_rowptr[NN] = sh[1023];
}

__global__ void csr_fill_kernel(const int* __restrict__ ei) {
    int i = blockIdx.x * blockDim.x + threadIdx.x;
    if (i < NN) g_dinv[i] = rsqrtf((float)g_deg[i]);
    if (i >= ET) return;
    int src, dst;
    if (i < EE) {
        src = min(max(ei[i], 0), NN - 1);
        dst = min(max(ei[EE + i], 0), NN - 1);
    } else {
        src = i - EE; dst = src;
    }
    int pos = g_rowptr[dst] + atomicAdd(&g_cursor[dst], 1);
    g_csr[pos] = src;
}

// ---------------- GEMM 1: hx = x @ W_gcn  (50000x32 @ 32x64) ----------------
__global__ void gemm1_kernel(const float* __restrict__ x,
                             const float* __restrict__ W) {
    __shared__ float Wsh[DIN * HID];        // 8 KB
    for (int i = threadIdx.x; i < DIN * HID; i += blockDim.x) Wsh[i] = W[i];
    __syncthreads();
    int gt   = blockIdx.x * blockDim.x + threadIdx.x;
    int warp = gt >> 5;
    int lane = gt & 31;
    if (warp >= NN) return;
    float xv = x[warp * DIN + lane];
    float a0 = 0.f, a1 = 0.f;
#pragma unroll
    for (int k = 0; k < 32; ++k) {
        float xk = __shfl_sync(0xffffffffu, xv, k);
        a0 += xk * Wsh[k * HID + lane];
        a1 += xk * Wsh[k * HID + 32 + lane];
    }
    g_hx[warp * HID + lane]      = a0;
    g_hx[warp * HID + 32 + lane] = a1;
}

// ---------------- GCN aggregation: one warp per dst node --------------------
__global__ void gcn_agg_kernel(const float* __restrict__ b_gcn) {
    int gt   = blockIdx.x * blockDim.x + threadIdx.x;
    int warp = gt >> 5;
    if (warp >= NN) return;
    int lane = gt & 31;
    int beg = g_rowptr[warp], end = g_rowptr[warp + 1];
    float dd = g_dinv[warp];
    float ax = 0.f, ay = 0.f;
    int src = g_csr[beg];                   // >=1 edge always (self loop)
    for (int j = beg; j < end; ++j) {
        int nsrc = (j + 1 < end) ? g_csr[j + 1] : 0;
        float w = g_dinv[src] * dd;
        float2 v = ((const float2*)(g_hx + (size_t)src * HID))[lane];
        ax += v.x * w;
        ay += v.y * w;
        src = nsrc;
    }
    float2 o;
    o.x = fmaxf(ax + b_gcn[2 * lane],     0.f);
    o.y = fmaxf(ay + b_gcn[2 * lane + 1], 0.f);
    ((float2*)(g_h1 + (size_t)warp * HID))[lane] = o;
}

// ---------------- GEMM 2: hg = h1 @ W_gat (50000x64 @ 64x256) ---------------
__global__ void gemm2_kernel(const float* __restrict__ Wg) {
    __shared__ float Wsh[64 * 128];         // 32 KB (half the columns)
    __shared__ float rsh[4 * 64];
    int tid = threadIdx.x;                  // 128
    int colOff = blockIdx.y * 128;
    for (int q = tid; q < 64 * 128; q += 128) {
        int k = q >> 7, c = q & 127;
        Wsh[q] = Wg[k * F2 + colOff + c];
    }
    __syncthreads();
    int rowBase = blockIdx.x * 64;
    for (int r0 = 0; r0 < 64; r0 += 4) {
        for (int q = tid; q < 256; q += 128) {
            int rr = q >> 6, kk = q & 63;
            int row = rowBase + r0 + rr;
            rsh[q] = (row < NN) ? g_h1[(size_t)row * HID + kk] : 0.f;
        }
        __syncthreads();
        float a0 = 0.f, a1 = 0.f, a2 = 0.f, a3 = 0.f;
#pragma unroll
        for (int k = 0; k < 64; ++k) {
            float w = Wsh[k * 128 + tid];
            a0 += rsh[k]       * w;
            a1 += rsh[64 + k]  * w;
            a2 += rsh[128 + k] * w;
            a3 += rsh[192 + k] * w;
        }
        int row = rowBase + r0;
        if (row     < NN) g_hg[(size_t)(row    ) * F2 + colOff + tid] = a0;
        if (row + 1 < NN) g_hg[(size_t)(row + 1) * F2 + colOff + tid] = a1;
        if (row + 2 < NN) g_hg[(size_t)(row + 2) * F2 + colOff + tid] = a2;
        if (row + 3 < NN) g_hg[(size_t)(row + 3) * F2 + colOff + tid] = a3;
        __syncthreads();
    }
}

// ---------------- attention dot products ------------------------------------
__global__ void attdot_kernel(const float* __restrict__ att_src,
                              const float* __restrict__ att_dst) {
    __shared__ float ash[F2], adh[F2];
    int tid = threadIdx.x;                  // 256
    ash[tid] = att_src[tid];
    adh[tid] = att_dst[tid];
    __syncthreads();
    int t = blockIdx.x * blockDim.x + tid;
    if (t >= NN * HEADS) return;
    int n = t >> 2, h = t & 3;
    const float4* row = (const float4*)(g_hg + (size_t)n * F2 + h * HID);
    float ss = 0.f, sd = 0.f;
#pragma unroll
    for (int i = 0; i < 16; ++i) {
        float4 v = row[i];
        int c = h * HID + i * 4;
        ss += v.x * ash[c] + v.y * ash[c + 1] + v.z * ash[c + 2] + v.w * ash[c + 3];
        sd += v.x * adh[c] + v.y * adh[c + 1] + v.z * adh[c + 2] + v.w * adh[c + 3];
    }
    g_as[t] = ss;
    g_ad[t] = sd;
}

// ---------------- GAT aggregation: warp per dst, online softmax -------------
__global__ void gat_agg_kernel(const float* __restrict__ b_gat) {
    int gt   = blockIdx.x * blockDim.x + threadIdx.x;
    int warp = gt >> 5;
    if (warp >= NN) return;
    int lane = gt & 31;
    int hd   = lane >> 3;                   // head for this lane
    int base = hd * HID + (lane & 7) * 8;   // 8 contiguous features
    float adv = g_ad[warp * HEADS + hd];
    int beg = g_rowptr[warp], end = g_rowptr[warp + 1];
    float m = -3.0e38f, s = 0.f;
    float acc[8];
#pragma unroll
    for (int k = 0; k < 8; ++k) acc[k] = 0.f;
    int src = g_csr[beg];
    for (int j = beg; j < end; ++j) {
        int nsrc = (j + 1 < end) ? g_csr[j + 1] : 0;
        float e = g_as[src * HEADS + hd] + adv;
        e = (e > 0.f) ? e : 0.2f * e;       // leaky relu, slope 0.2
        float nm = fmaxf(m, e);
        float sc = __expf(m - nm);          // first iter: exp(-huge) = 0
        float w  = __expf(e - nm);
        const float4* p = (const float4*)(g_hg + (size_t)src * F2 + base);
        float4 v0 = p[0], v1 = p[1];
        s = s * sc + w;
        acc[0] = acc[0] * sc + w * v0.x;
        acc[1] = acc[1] * sc + w * v0.y;
        acc[2] = acc[2] * sc + w * v0.z;
        acc[3] = acc[3] * sc + w * v0.w;
        acc[4] = acc[4] * sc + w * v1.x;
        acc[5] = acc[5] * sc + w * v1.y;
        acc[6] = acc[6] * sc + w * v1.z;
        acc[7] = acc[7] * sc + w * v1.w;
        m = nm;
        src = nsrc;
    }
    float inv = 1.f / s;
    float* o = g_out2 + (size_t)warp * F2 + base;
#pragma unroll
    for (int k = 0; k < 8; ++k)
        o[k] = fmaxf(acc[k] * inv + b_gat[base + k], 0.f);
}

// ---------------- GEMM 3: out = out2 @ W_fc + b_fc (50000x256 @ 256x32) -----
__global__ void gemm3_kernel(const float* __restrict__ Wfc,
                             const float* __restrict__ bfc,
                             float* __restrict__ out) {
    __shared__ float Wsh[F2 * DOUT];        // 32 KB
    __shared__ float insh[8 * F2];          //  8 KB
    int tid = threadIdx.x;                  // 256
    for (int q = tid; q < F2 * DOUT; q += 256) Wsh[q] = Wfc[q];
    __syncthreads();
    int rowBase = blockIdx.x * 128;
    int r = tid >> 5, c = tid & 31;
    float bv = bfc[c];
    for (int g = 0; g < 128; g += 8) {
        for (int q = tid; q < 8 * F2; q += 256) {
            int rr = q >> 8, kk = q & 255;
            int row = rowBase + g + rr;
            insh[q] = (row < NN) ? g_out2[(size_t)row * F2 + kk] : 0.f;
        }
        __syncthreads();
        float a = 0.f;
#pragma unroll 8
        for (int k = 0; k < F2; ++k) a += insh[r * F2 + k] * Wsh[k * DOUT + c];
        int row = rowBase + g + r;
        if (row < NN) out[row * DOUT + c] = a + bv;
        __syncthreads();
    }
}

// ---------------- launch ----------------------------------------------------
extern "C" void kernel_launch(void* const* d_in, const int* in_sizes, int n_in,
                              void* d_out, int out_size) {
    const float* x       = (const float*)d_in[0];
    const int*   ei      = (const int*)  d_in[1];   // int32! JAX x64 is off
    const float* W_gcn   = (const float*)d_in[2];
    const float* b_gcn   = (const float*)d_in[3];
    const float* W_gat   = (const float*)d_in[4];
    const float* att_src = (const float*)d_in[5];
    const float* att_dst = (const float*)d_in[6];
    const float* b_gat   = (const float*)d_in[7];
    const float* W_fc    = (const float*)d_in[8];
    const float* b_fc    = (const float*)d_in[9];
    float*       out     = (float*)d_out;

    init_kernel    <<<(NN + 255) / 256, 256>>>();
    deg_kernel     <<<(EE + 255) / 256, 256>>>(ei);
    scan_kernel    <<<1, 1024>>>();
    csr_fill_kernel<<<(ET + 255) / 256, 256>>>(ei);

    gemm1_kernel   <<<(NN * 32 + 255) / 256, 256>>>(x, W_gcn);
    gcn_agg_kernel <<<(NN * 32 + 255) / 256, 256>>>(b_gcn);

    gemm2_kernel   <<<dim3((NN + 63) / 64, 2), 128>>>(W_gat);
    attdot_kernel  <<<(NN * HEADS + 255) / 256, 256>>>(att_src, att_dst);
    gat_agg_kernel <<<(NN * 32 + 255) / 256, 256>>>(b_gat);

    gemm3_kernel   <<<(NN + 127) / 128, 256>>>(W_fc, b_fc, out);
}

// round 3
// speedup vs baseline: 1.0969x; 1.0969x over previous
#include <cuda_runtime.h>
#include <cuda_fp16.h>

// Problem constants (fixed by the dataset)
constexpr int NN   = 50000;
constexpr int EE   = 1600000;
constexpr int ET   = EE + NN;     // edges + self loops
constexpr int DIN  = 32;
constexpr int HID  = 64;
constexpr int HEADS= 4;
constexpr int F2   = HEADS * HID; // 256
constexpr int DOUT = 32;

// ---------------- scratch (device globals; no allocation allowed) -----------
__device__ __half g_hx [NN * HID];   // x @ W_gcn   (half, gather table)
__device__ float  g_h1 [NN * HID];   // relu(gcn)
__device__ float  g_hg [NN * F2];    // h1 @ W_gat  (fp32, for attdot)
__device__ __half g_hgh[NN * F2];    // h1 @ W_gat  (half, gather table)
__device__ float  g_out2[NN * F2];   // relu(gat)
__device__ float  g_as [NN * HEADS];
__device__ float  g_ad [NN * HEADS];
__device__ float  g_dinv[NN];
__device__ int    g_deg [NN];
__device__ int    g_rowptr[NN + 1];
__device__ int    g_cursor[NN];
__device__ int    g_csr[ET];

// ---------------- CSR build -------------------------------------------------
__global__ void init_kernel() {
    int i = blockIdx.x * blockDim.x + threadIdx.x;
    if (i < NN) { g_deg[i] = 1; g_cursor[i] = 0; }   // self-loop counted
}

__global__ void deg_kernel(const int* __restrict__ ei) {
    int i = blockIdx.x * blockDim.x + threadIdx.x;
    if (i >= EE) return;
    int d = ei[EE + i];
    d = min(max(d, 0), NN - 1);             // defensive clamp
    atomicAdd(&g_deg[d], 1);
}

// single-block exclusive scan over degrees -> rowptr
__global__ void scan_kernel() {
    __shared__ int sh[1024];
    const int C = 49;                       // 1024*49 = 50176 >= NN
    int t = threadIdx.x;
    int start = t * C;
    int end   = min(start + C, NN);
    int sum = 0;
    for (int i = start; i < end; ++i) sum += g_deg[i];
    sh[t] = sum;
    __syncthreads();
    for (int off = 1; off < 1024; off <<= 1) {
        int v = (t >= off) ? sh[t - off] : 0;
        __syncthreads();
        sh[t] += v;
        __syncthreads();
    }
    int run = sh[t] - sum;                  // exclusive prefix
    for (int i = start; i < end; ++i) { g_rowptr[i] = run; run += g_deg[i]; }
    if (t == 1023) g_rowptr[NN] = sh[1023];
}

__global__ void csr_fill_kernel(const int* __restrict__ ei) {
    int i = blockIdx.x * blockDim.x + threadIdx.x;
    if (i < NN) g_dinv[i] = rsqrtf((float)g_deg[i]);
    if (i >= ET) return;
    int src, dst;
    if (i < EE) {
        src = min(max(ei[i], 0), NN - 1);
        dst = min(max(ei[EE + i], 0), NN - 1);
    } else {
        src = i - EE; dst = src;
    }
    int pos = g_rowptr[dst] + atomicAdd(&g_cursor[dst], 1);
    g_csr[pos] = src;
}

// ---------------- GEMM 1: hx = x @ W_gcn  (50000x32 @ 32x64), half out ------
__global__ void gemm1_kernel(const float* __restrict__ x,
                             const float* __restrict__ W) {
    __shared__ float Wsh[DIN * HID];        // 8 KB
    for (int i = threadIdx.x; i < DIN * HID; i += blockDim.x) Wsh[i] = W[i];
    __syncthreads();
    int gt   = blockIdx.x * blockDim.x + threadIdx.x;
    int warp = gt >> 5;
    int lane = gt & 31;
    if (warp >= NN) return;
    float xv = x[warp * DIN + lane];
    float a0 = 0.f, a1 = 0.f;
#pragma unroll
    for (int k = 0; k < 32; ++k) {
        float xk = __shfl_sync(0xffffffffu, xv, k);
        a0 += xk * Wsh[k * HID + lane];
        a1 += xk * Wsh[k * HID + 32 + lane];
    }
    g_hx[warp * HID + lane]      = __float2half(a0);
    g_hx[warp * HID + 32 + lane] = __float2half(a1);
}

// ---------------- GCN aggregation: one warp per dst node, half gathers ------
__global__ void gcn_agg_kernel(const float* __restrict__ b_gcn) {
    int gt   = blockIdx.x * blockDim.x + threadIdx.x;
    int warp = gt >> 5;
    if (warp >= NN) return;
    int lane = gt & 31;
    int beg = g_rowptr[warp], end = g_rowptr[warp + 1];
    float dd = g_dinv[warp];
    float ax = 0.f, ay = 0.f;
    const __half2* hx2 = (const __half2*)g_hx;
    int j = beg;
    for (; j + 2 <= end; j += 2) {
        int s0 = g_csr[j], s1 = g_csr[j + 1];
        float w0 = g_dinv[s0] * dd;
        float w1 = g_dinv[s1] * dd;
        float2 a = __half22float2(hx2[s0 * 32 + lane]);
        float2 b = __half22float2(hx2[s1 * 32 + lane]);
        ax += a.x * w0 + b.x * w1;
        ay += a.y * w0 + b.y * w1;
    }
    if (j < end) {
        int s0 = g_csr[j];
        float w0 = g_dinv[s0] * dd;
        float2 a = __half22float2(hx2[s0 * 32 + lane]);
        ax += a.x * w0;
        ay += a.y * w0;
    }
    float2 o;
    o.x = fmaxf(ax + b_gcn[2 * lane],     0.f);
    o.y = fmaxf(ay + b_gcn[2 * lane + 1], 0.f);
    ((float2*)(g_h1 + (size_t)warp * HID))[lane] = o;
}

// ---------------- GEMM 2: hg = h1 @ W_gat (50000x64 @ 64x256) ---------------
__global__ void gemm2_kernel(const float* __restrict__ Wg) {
    __shared__ float Wsh[64 * 128];         // 32 KB (half the columns)
    __shared__ float rsh[4 * 64];
    int tid = threadIdx.x;                  // 128
    int colOff = blockIdx.y * 128;
    for (int q = tid; q < 64 * 128; q += 128) {
        int k = q >> 7, c = q & 127;
        Wsh[q] = Wg[k * F2 + colOff + c];
    }
    __syncthreads();
    int rowBase = blockIdx.x * 64;
    for (int r0 = 0; r0 < 64; r0 += 4) {
        for (int q = tid; q < 256; q += 128) {
            int rr = q >> 6, kk = q & 63;
            int row = rowBase + r0 + rr;
            rsh[q] = (row < NN) ? g_h1[(size_t)row * HID + kk] : 0.f;
        }
        __syncthreads();
        float a0 = 0.f, a1 = 0.f, a2 = 0.f, a3 = 0.f;
#pragma unroll
        for (int k = 0; k < 64; ++k) {
            float w = Wsh[k * 128 + tid];
            a0 += rsh[k]       * w;
            a1 += rsh[64 + k]  * w;
            a2 += rsh[128 + k] * w;
            a3 += rsh[192 + k] * w;
        }
        int row = rowBase + r0;
        if (row < NN) {
            size_t p = (size_t)row * F2 + colOff + tid;
            g_hg[p] = a0;  g_hgh[p] = __float2half(a0);
        }
        if (row + 1 < NN) {
            size_t p = (size_t)(row + 1) * F2 + colOff + tid;
            g_hg[p] = a1;  g_hgh[p] = __float2half(a1);
        }
        if (row + 2 < NN) {
            size_t p = (size_t)(row + 2) * F2 + colOff + tid;
            g_hg[p] = a2;  g_hgh[p] = __float2half(a2);
        }
        if (row + 3 < NN) {
            size_t p = (size_t)(row + 3) * F2 + colOff + tid;
            g_hg[p] = a3;  g_hgh[p] = __float2half(a3);
        }
        __syncthreads();
    }
}

// ---------------- attention dot products (from fp32 hg) ---------------------
__global__ void attdot_kernel(const float* __restrict__ att_src,
                              const float* __restrict__ att_dst) {
    __shared__ float ash[F2], adh[F2];
    int tid = threadIdx.x;                  // 256
    ash[tid] = att_src[tid];
    adh[tid] = att_dst[tid];
    __syncthreads();
    int t = blockIdx.x * blockDim.x + tid;
    if (t >= NN * HEADS) return;
    int n = t >> 2, h = t & 3;
    const float4* row = (const float4*)(g_hg + (size_t)n * F2 + h * HID);
    float ss = 0.f, sd = 0.f;
#pragma unroll
    for (int i = 0; i < 16; ++i) {
        float4 v = row[i];
        int c = h * HID + i * 4;
        ss += v.x * ash[c] + v.y * ash[c + 1] + v.z * ash[c + 2] + v.w * ash[c + 3];
        sd += v.x * adh[c] + v.y * adh[c + 1] + v.z * adh[c + 2] + v.w * adh[c + 3];
    }
    g_as[t] = ss;
    g_ad[t] = sd;
}

// ---------------- GAT aggregation: warp per dst, online softmax, half -------
__device__ __forceinline__ float lrelu(float e) {
    return (e > 0.f) ? e : 0.2f * e;
}

__global__ void gat_agg_kernel(const float* __restrict__ b_gat) {
    int gt   = blockIdx.x * blockDim.x + threadIdx.x;
    int warp = gt >> 5;
    if (warp >= NN) return;
    int lane = gt & 31;
    int hd   = lane >> 3;                   // head for this lane
    int base = hd * HID + (lane & 7) * 8;   // 8 contiguous features
    float adv = g_ad[warp * HEADS + hd];
    int beg = g_rowptr[warp], end = g_rowptr[warp + 1];
    float m = -3.0e38f, s = 0.f;
    float acc[8];
#pragma unroll
    for (int k = 0; k < 8; ++k) acc[k] = 0.f;

    int j = beg;
    for (; j + 2 <= end; j += 2) {
        int s0 = g_csr[j], s1 = g_csr[j + 1];
        float e0 = lrelu(g_as[s0 * HEADS + hd] + adv);
        float e1 = lrelu(g_as[s1 * HEADS + hd] + adv);
        int4 p0 = *(const int4*)(g_hgh + (size_t)s0 * F2 + base);
        int4 p1 = *(const int4*)(g_hgh + (size_t)s1 * F2 + base);
        float nm = fmaxf(m, fmaxf(e0, e1));
        float sc = __expf(m - nm);
        float w0 = __expf(e0 - nm);
        float w1 = __expf(e1 - nm);
        s = s * sc + w0 + w1;
        const __half2* h0 = (const __half2*)&p0;
        const __half2* h1 = (const __half2*)&p1;
#pragma unroll
        for (int k = 0; k < 4; ++k) {
            float2 a = __half22float2(h0[k]);
            float2 b = __half22float2(h1[k]);
            acc[2 * k]     = acc[2 * k]     * sc + w0 * a.x + w1 * b.x;
            acc[2 * k + 1] = acc[2 * k + 1] * sc + w0 * a.y + w1 * b.y;
        }
        m = nm;
    }
    if (j < end) {
        int s0 = g_csr[j];
        float e0 = lrelu(g_as[s0 * HEADS + hd] + adv);
        int4 p0 = *(const int4*)(g_hgh + (size_t)s0 * F2 + base);
        float nm = fmaxf(m, e0);
        float sc = __expf(m - nm);
        float w0 = __expf(e0 - nm);
        s = s * sc + w0;
        const __half2* h0 = (const __half2*)&p0;
#pragma unroll
        for (int k = 0; k < 4; ++k) {
            float2 a = __half22float2(h0[k]);
            acc[2 * k]     = acc[2 * k]     * sc + w0 * a.x;
            acc[2 * k + 1] = acc[2 * k + 1] * sc + w0 * a.y;
        }
    }
    float inv = 1.f / s;
    float* o = g_out2 + (size_t)warp * F2 + base;
#pragma unroll
    for (int k = 0; k < 8; ++k)
        o[k] = fmaxf(acc[k] * inv + b_gat[base + k], 0.f);
}

// ---------------- GEMM 3: out = out2 @ W_fc + b_fc (50000x256 @ 256x32) -----
__global__ void gemm3_kernel(const float* __restrict__ Wfc,
                             const float* __restrict__ bfc,
                             float* __restrict__ out) {
    __shared__ float Wsh[F2 * DOUT];        // 32 KB
    __shared__ float insh[8 * F2];          //  8 KB
    int tid = threadIdx.x;                  // 256
    for (int q = tid; q < F2 * DOUT; q += 256) Wsh[q] = Wfc[q];
    __syncthreads();
    int rowBase = blockIdx.x * 128;
    int r = tid >> 5, c = tid & 31;
    float bv = bfc[c];
    for (int g = 0; g < 128; g += 8) {
        for (int q = tid; q < 8 * F2; q += 256) {
            int rr = q >> 8, kk = q & 255;
            int row = rowBase + g + rr;
            insh[q] = (row < NN) ? g_out2[(size_t)row * F2 + kk] : 0.f;
        }
        __syncthreads();
        float a = 0.f;
#pragma unroll 8
        for (int k = 0; k < F2; ++k) a += insh[r * F2 + k] * Wsh[k * DOUT + c];
        int row = rowBase + g + r;
        if (row < NN) out[row * DOUT + c] = a + bv;
        __syncthreads();
    }
}

// ---------------- launch ----------------------------------------------------
extern "C" void kernel_launch(void* const* d_in, const int* in_sizes, int n_in,
                              void* d_out, int out_size) {
    const float* x       = (const float*)d_in[0];
    const int*   ei      = (const int*)  d_in[1];   // int32 (JAX x64 off)
    const float* W_gcn   = (const float*)d_in[2];
    const float* b_gcn   = (const float*)d_in[3];
    const float* W_gat   = (const float*)d_in[4];
    const float* att_src = (const float*)d_in[5];
    const float* att_dst = (const float*)d_in[6];
    const float* b_gat   = (const float*)d_in[7];
    const float* W_fc    = (const float*)d_in[8];
    const float* b_fc    = (const float*)d_in[9];
    float*       out     = (float*)d_out;

    init_kernel    <<<(NN + 255) / 256, 256>>>();
    deg_kernel     <<<(EE + 255) / 256, 256>>>(ei);
    scan_kernel    <<<1, 1024>>>();
    csr_fill_kernel<<<(ET + 255) / 256, 256>>>(ei);

    gemm1_kernel   <<<(NN * 32 + 255) / 256, 256>>>(x, W_gcn);
    gcn_agg_kernel <<<(NN * 32 + 255) / 256, 256>>>(b_gcn);

    gemm2_kernel   <<<dim3((NN + 63) / 64, 2), 128>>>(W_gat);
    attdot_kernel  <<<(NN * HEADS + 255) / 256, 256>>>(att_src, att_dst);
    gat_agg_kernel <<<(NN * 32 + 255) / 256, 256>>>(b_gat);

    gemm3_kernel   <<<(NN + 127) / 128, 256>>>(W_fc, b_fc, out);
}